// round 1
// baseline (speedup 1.0000x reference)
#include <cuda_runtime.h>

#define SQ   2048
#define HID  2560
#define NH   16
#define NKV  4
#define HD   128
#define QKV_DIM (NH*HD + 2*NKV*HD)   // 3072
#define EPS  1e-6f
#define ATT_SCALE 0.08838834764831845f  // 1/sqrt(128)

// ---------------- scratch (device globals, no allocation) ----------------
__device__ float g_qkv[(size_t)SQ * QKV_DIM];            // 25 MB
__device__ float g_scores[(size_t)NH * SQ * SQ];         // 256 MB
__device__ float g_att[(size_t)SQ * NH * HD];            // 16 MB

// ---------------- generic tiled fp32 GEMM ----------------
// C[m,n] = alpha * sum_k A[m,k] * Bop[k,n]
//   NT=true : B is row-major [N,K]  (Bop[k,n] = B[n*ldb+k])
//   NT=false: B is row-major [K,N]  (Bop[k,n] = B[k*ldb+n])
// Batch: bz over gridDim.z; A += bz*aBatch; B += (bz/bDiv)*bBatch; C += bz*cBatch
// CAUSAL: skip N-tiles entirely above the diagonal (bx > by).
template<bool NT, bool CAUSAL>
__global__ void __launch_bounds__(256) gemm_kernel(
    const float* __restrict__ A, const float* __restrict__ B, float* __restrict__ C,
    int M, int N, int K, int lda, int ldb, int ldc,
    long long aBatch, long long bBatch, int bDiv, long long cBatch, float alpha)
{
    const int bx = blockIdx.x, by = blockIdx.y, bz = blockIdx.z;
    if (CAUSAL && bx > by) return;

    A += (long long)bz * aBatch;
    B += (long long)(bz / bDiv) * bBatch;
    C += (long long)bz * cBatch;

    __shared__ float As[8][128];
    __shared__ float Bs[8][128];

    const int t  = threadIdx.x;
    const int m0 = by * 128, n0 = bx * 128;
    const int ty = t >> 4, tx = t & 15;

    float acc[8][8];
    #pragma unroll
    for (int i = 0; i < 8; i++)
        #pragma unroll
        for (int j = 0; j < 8; j++) acc[i][j] = 0.f;

    const int ldRow = t >> 1;          // 0..127
    const int ldK   = (t & 1) * 4;     // 0 or 4

    for (int k0 = 0; k0 < K; k0 += 8) {
        // A tile: [128 rows x 8 k], k-contiguous
        float4 a4 = *(const float4*)(A + (long long)(m0 + ldRow) * lda + k0 + ldK);
        As[ldK + 0][ldRow] = a4.x;
        As[ldK + 1][ldRow] = a4.y;
        As[ldK + 2][ldRow] = a4.z;
        As[ldK + 3][ldRow] = a4.w;

        if (NT) {
            float4 b4 = *(const float4*)(B + (long long)(n0 + ldRow) * ldb + k0 + ldK);
            Bs[ldK + 0][ldRow] = b4.x;
            Bs[ldK + 1][ldRow] = b4.y;
            Bs[ldK + 2][ldRow] = b4.z;
            Bs[ldK + 3][ldRow] = b4.w;
        } else {
            const int kr = t >> 5;            // 0..7
            const int nc = (t & 31) * 4;      // 0..124
            float4 b4 = *(const float4*)(B + (long long)(k0 + kr) * ldb + n0 + nc);
            *(float4*)&Bs[kr][nc] = b4;
        }
        __syncthreads();

        #pragma unroll
        for (int kk = 0; kk < 8; kk++) {
            float a[8], b[8];
            #pragma unroll
            for (int i = 0; i < 8; i++) a[i] = As[kk][ty * 8 + i];
            #pragma unroll
            for (int j = 0; j < 8; j++) b[j] = Bs[kk][tx * 8 + j];
            #pragma unroll
            for (int i = 0; i < 8; i++)
                #pragma unroll
                for (int j = 0; j < 8; j++) acc[i][j] += a[i] * b[j];
        }
        __syncthreads();
    }

    #pragma unroll
    for (int i = 0; i < 8; i++) {
        float* crow = C + (long long)(m0 + ty * 8 + i) * ldc + n0 + tx * 8;
        #pragma unroll
        for (int j = 0; j < 8; j += 4) {
            float4 o;
            o.x = acc[i][j + 0] * alpha;
            o.y = acc[i][j + 1] * alpha;
            o.z = acc[i][j + 2] * alpha;
            o.w = acc[i][j + 3] * alpha;
            *(float4*)(crow + j) = o;
        }
    }
}

// ---------------- fused RMSNorm + RoPE, in-place on g_qkv ----------------
// grid: (SQ, NH+NKV). blockIdx.y < NH -> q head; else k head. 128 threads.
__global__ void __launch_bounds__(128) norm_rope_kernel(
    const float* __restrict__ qw, const float* __restrict__ kw,
    const float* __restrict__ cosT, const float* __restrict__ sinT,
    const int* __restrict__ positions)
{
    const int tok = blockIdx.x;
    const int hh  = blockIdx.y;
    const int d   = threadIdx.x;

    float* ptr;
    const float* w;
    if (hh < NH) { ptr = g_qkv + (long long)tok * QKV_DIM + hh * HD;            w = qw; }
    else         { ptr = g_qkv + (long long)tok * QKV_DIM + NH*HD + (hh-NH)*HD; w = kw; }

    __shared__ float x[HD];
    __shared__ float red[4];

    float v = ptr[d];
    float ss = v * v;
    #pragma unroll
    for (int o = 16; o > 0; o >>= 1) ss += __shfl_xor_sync(0xffffffffu, ss, o);
    if ((d & 31) == 0) red[d >> 5] = ss;
    __syncthreads();
    float tot = red[0] + red[1] + red[2] + red[3];
    float r = rsqrtf(tot * (1.0f / HD) + EPS);
    x[d] = v * r * w[d];
    __syncthreads();

    const int pos = positions[tok];
    const int p = d >> 1;
    const float c = cosT[pos * (HD/2) + p];
    const float s = sinT[pos * (HD/2) + p];
    float out;
    if ((d & 1) == 0) out = x[d] * c - x[d + 1] * s;
    else              out = x[d - 1] * s + x[d] * c;
    ptr[d] = out;
}

// ---------------- causal softmax, zeroes masked region ----------------
// grid: (SQ, NH), 256 threads. Row length n = q+1; scores beyond n are garbage
// (causally-skipped GEMM tiles) and are set to 0 so the PV GEMM can run dense.
__global__ void __launch_bounds__(256) softmax_kernel()
{
    const int q = blockIdx.x, h = blockIdx.y;
    float* row = g_scores + ((long long)h * SQ + q) * SQ;
    const int n = q + 1;
    const int t = threadIdx.x;

    __shared__ float red[8];

    // max
    float mx = -1e30f;
    for (int k = t; k < n; k += 256) mx = fmaxf(mx, row[k]);
    #pragma unroll
    for (int o = 16; o > 0; o >>= 1) mx = fmaxf(mx, __shfl_xor_sync(0xffffffffu, mx, o));
    if ((t & 31) == 0) red[t >> 5] = mx;
    __syncthreads();
    mx = red[0];
    #pragma unroll
    for (int i = 1; i < 8; i++) mx = fmaxf(mx, red[i]);
    __syncthreads();

    // exp + sum
    float sum = 0.f;
    for (int k = t; k < n; k += 256) {
        float e = expf(row[k] - mx);
        row[k] = e;
        sum += e;
    }
    #pragma unroll
    for (int o = 16; o > 0; o >>= 1) sum += __shfl_xor_sync(0xffffffffu, sum, o);
    if ((t & 31) == 0) red[t >> 5] = sum;
    __syncthreads();
    sum = red[0] + red[1] + red[2] + red[3] + red[4] + red[5] + red[6] + red[7];
    const float inv = 1.0f / sum;

    for (int k = t; k < SQ; k += 256) {
        if (k < n) row[k] *= inv;
        else       row[k]  = 0.f;
    }
}

// ---------------- launch ----------------
extern "C" void kernel_launch(void* const* d_in, const int* in_sizes, int n_in,
                              void* d_out, int out_size)
{
    const float* hs     = (const float*)d_in[0];   // [2048, 2560]
    const float* w_qkv  = (const float*)d_in[1];   // [3072, 2560]
    const float* w_o    = (const float*)d_in[2];   // [2560, 2048]
    const float* qnw    = (const float*)d_in[3];   // [128]
    const float* knw    = (const float*)d_in[4];   // [128]
    const float* cosT   = (const float*)d_in[5];   // [4096, 64]
    const float* sinT   = (const float*)d_in[6];   // [4096, 64]
    // d_in[7], d_in[8]: k_cache/v_cache — identity round-trip, unused
    const int* positions = (const int*)d_in[9];    // [2048]
    // d_in[10]: block_table — unused
    float* out = (float*)d_out;                    // [2048, 2560]

    float *qkv, *scores, *att;
    cudaGetSymbolAddress((void**)&qkv,    g_qkv);
    cudaGetSymbolAddress((void**)&scores, g_scores);
    cudaGetSymbolAddress((void**)&att,    g_att);

    // 1) QKV projection: [2048,3072] = hs @ w_qkv^T  (NT)
    gemm_kernel<true, false><<<dim3(QKV_DIM/128, SQ/128, 1), 256>>>(
        hs, w_qkv, qkv, SQ, QKV_DIM, HID, HID, HID, QKV_DIM,
        0, 0, 1, 0, 1.0f);

    // 2) RMSNorm + RoPE in-place on q and k portions of qkv
    norm_rope_kernel<<<dim3(SQ, NH + NKV), 128>>>(qnw, knw, cosT, sinT, positions);

    // 3) scores[h] = (Q_h @ K_{h/4}^T) * SCALE, causal tiles skipped  (NT, batched over heads)
    gemm_kernel<true, true><<<dim3(SQ/128, SQ/128, NH), 256>>>(
        qkv, qkv + NH*HD, scores, SQ, SQ, HD, QKV_DIM, QKV_DIM, SQ,
        HD, HD, NH/NKV, (long long)SQ * SQ, ATT_SCALE);

    // 4) causal softmax (also zeroes masked/garbage region)
    softmax_kernel<<<dim3(SQ, NH), 256>>>();

    // 5) att[h] = P_h @ V_{h/4}  (NN, batched over heads)
    gemm_kernel<false, false><<<dim3(HD/128, SQ/128, NH), 256>>>(
        scores, qkv + NH*HD + NKV*HD, att, SQ, HD, SQ, SQ, QKV_DIM, NH*HD,
        (long long)SQ * SQ, HD, NH/NKV, HD, 1.0f);

    // 6) output projection: [2048,2560] = att @ w_o^T  (NT)
    gemm_kernel<true, false><<<dim3(HID/128, SQ/128, 1), 256>>>(
        att, w_o, out, SQ, HID, NH*HD, NH*HD, NH*HD, HID,
        0, 0, 1, 0, 1.0f);
}

// round 2
// speedup vs baseline: 2.0167x; 2.0167x over previous
#include <cuda_runtime.h>
#include <cstdint>

#define SQ   2048
#define HID  2560
#define NH   16
#define NKV  4
#define HD   128
#define QKV_DIM (NH*HD + 2*NKV*HD)   // 3072
#define EPS  1e-6f
#define ATT_SCALE 0.08838834764831845f  // 1/sqrt(128)

// ---------------- scratch (device globals, no allocation) ----------------
__device__ float g_qkv[(size_t)SQ * QKV_DIM];            // 25 MB
__device__ float g_scores[(size_t)NH * SQ * SQ];         // 256 MB
__device__ float g_att[(size_t)SQ * NH * HD];            // 16 MB

__device__ __forceinline__ uint32_t f2tf32(float x) {
    uint32_t u;
    asm("cvt.rna.tf32.f32 %0, %1;" : "=r"(u) : "f"(x));
    return u;
}

__device__ __forceinline__ void mma_tf32(float* d, const uint32_t* a, const uint32_t* b) {
    asm volatile(
        "mma.sync.aligned.m16n8k8.row.col.f32.tf32.tf32.f32 "
        "{%0,%1,%2,%3}, {%4,%5,%6,%7}, {%8,%9}, {%0,%1,%2,%3};\n"
        : "+f"(d[0]), "+f"(d[1]), "+f"(d[2]), "+f"(d[3])
        : "r"(a[0]), "r"(a[1]), "r"(a[2]), "r"(a[3]), "r"(b[0]), "r"(b[1]));
}

// ---------------- tf32 tensor-core GEMM ----------------
// C[m,n] = alpha * sum_k A[m,k] * Bop[k,n]
//   NT=true : B row-major [N,K]; NT=false: B row-major [K,N]
// CAUSAL : skip N-tiles with bx > by (upper-triangular block skip)
// CAUSALK: bound K at (by+1)*128 (for PV where P is causally zero)
// 128x128x32 tile, 256 threads, warp = 64x32 via 4x4 m16n8k8.
template<bool NT, bool CAUSAL, bool CAUSALK>
__global__ void __launch_bounds__(256, 2) mma_gemm(
    const float* __restrict__ A, const float* __restrict__ B, float* __restrict__ C,
    int K, int lda, int ldb, int ldc,
    long long aBatch, long long bBatch, int bDiv, long long cBatch, float alpha)
{
    const int bx = blockIdx.x, by = blockIdx.y, bz = blockIdx.z;
    if (CAUSAL && bx > by) return;

    A += (long long)bz * aBatch;
    B += (long long)(bz / bDiv) * bBatch;
    C += (long long)bz * cBatch;

    // [k][m] layout, row stride 136 words -> fragment LDS bank-conflict-free
    __shared__ uint32_t As[32][136];
    __shared__ uint32_t Bs[32][136];

    const int t    = threadIdx.x;
    const int lane = t & 31, wid = t >> 5;
    const int wm   = (wid & 1) * 64;     // warp M offset (2 warps in M)
    const int wn   = (wid >> 1) * 32;    // warp N offset (4 warps in N)
    const int m0   = by * 128, n0 = bx * 128;
    const int grp  = lane >> 2, tid4 = lane & 3;

    float acc[4][4][4];
    #pragma unroll
    for (int i = 0; i < 4; i++)
        #pragma unroll
        for (int j = 0; j < 4; j++)
            #pragma unroll
            for (int r = 0; r < 4; r++) acc[i][j][r] = 0.f;

    const int lrow  = t & 127;          // row within tile for A/B-NT loads
    const int lhalf = (t >> 7) * 16;    // which 16-wide k half

    const int Kend = CAUSALK ? ((by + 1) * 128 < K ? (by + 1) * 128 : K) : K;

    for (int k0 = 0; k0 < Kend; k0 += 32) {
        // ---- load A tile: rows m0+lrow, k cols [k0+lhalf, +16) ----
        {
            const float* Ap = A + (long long)(m0 + lrow) * lda + k0 + lhalf;
            float4 v0 = *(const float4*)(Ap + 0);
            float4 v1 = *(const float4*)(Ap + 4);
            float4 v2 = *(const float4*)(Ap + 8);
            float4 v3 = *(const float4*)(Ap + 12);
            As[lhalf +  0][lrow] = f2tf32(v0.x); As[lhalf +  1][lrow] = f2tf32(v0.y);
            As[lhalf +  2][lrow] = f2tf32(v0.z); As[lhalf +  3][lrow] = f2tf32(v0.w);
            As[lhalf +  4][lrow] = f2tf32(v1.x); As[lhalf +  5][lrow] = f2tf32(v1.y);
            As[lhalf +  6][lrow] = f2tf32(v1.z); As[lhalf +  7][lrow] = f2tf32(v1.w);
            As[lhalf +  8][lrow] = f2tf32(v2.x); As[lhalf +  9][lrow] = f2tf32(v2.y);
            As[lhalf + 10][lrow] = f2tf32(v2.z); As[lhalf + 11][lrow] = f2tf32(v2.w);
            As[lhalf + 12][lrow] = f2tf32(v3.x); As[lhalf + 13][lrow] = f2tf32(v3.y);
            As[lhalf + 14][lrow] = f2tf32(v3.z); As[lhalf + 15][lrow] = f2tf32(v3.w);
        }
        // ---- load B tile ----
        if (NT) {
            const float* Bp = B + (long long)(n0 + lrow) * ldb + k0 + lhalf;
            float4 v0 = *(const float4*)(Bp + 0);
            float4 v1 = *(const float4*)(Bp + 4);
            float4 v2 = *(const float4*)(Bp + 8);
            float4 v3 = *(const float4*)(Bp + 12);
            Bs[lhalf +  0][lrow] = f2tf32(v0.x); Bs[lhalf +  1][lrow] = f2tf32(v0.y);
            Bs[lhalf +  2][lrow] = f2tf32(v0.z); Bs[lhalf +  3][lrow] = f2tf32(v0.w);
            Bs[lhalf +  4][lrow] = f2tf32(v1.x); Bs[lhalf +  5][lrow] = f2tf32(v1.y);
            Bs[lhalf +  6][lrow] = f2tf32(v1.z); Bs[lhalf +  7][lrow] = f2tf32(v1.w);
            Bs[lhalf +  8][lrow] = f2tf32(v2.x); Bs[lhalf +  9][lrow] = f2tf32(v2.y);
            Bs[lhalf + 10][lrow] = f2tf32(v2.z); Bs[lhalf + 11][lrow] = f2tf32(v2.w);
            Bs[lhalf + 12][lrow] = f2tf32(v3.x); Bs[lhalf + 13][lrow] = f2tf32(v3.y);
            Bs[lhalf + 14][lrow] = f2tf32(v3.z); Bs[lhalf + 15][lrow] = f2tf32(v3.w);
        } else {
            const int kr = t >> 3, nc = (t & 7) * 4;
            const float* Bp = B + (long long)(k0 + kr) * ldb + n0 + nc;
            #pragma unroll
            for (int i = 0; i < 4; i++) {
                float4 v = *(const float4*)(Bp + i * 32);
                uint4 u;
                u.x = f2tf32(v.x); u.y = f2tf32(v.y);
                u.z = f2tf32(v.z); u.w = f2tf32(v.w);
                *(uint4*)&Bs[kr][nc + i * 32] = u;
            }
        }
        __syncthreads();

        #pragma unroll
        for (int j = 0; j < 4; j++) {
            const int kb = j * 8;
            uint32_t af[4][4], bf[4][2];
            #pragma unroll
            for (int mt = 0; mt < 4; mt++) {
                const int mr = wm + mt * 16 + grp;
                af[mt][0] = As[kb + tid4    ][mr];
                af[mt][1] = As[kb + tid4    ][mr + 8];
                af[mt][2] = As[kb + tid4 + 4][mr];
                af[mt][3] = As[kb + tid4 + 4][mr + 8];
            }
            #pragma unroll
            for (int nt = 0; nt < 4; nt++) {
                const int nc2 = wn + nt * 8 + grp;
                bf[nt][0] = Bs[kb + tid4    ][nc2];
                bf[nt][1] = Bs[kb + tid4 + 4][nc2];
            }
            #pragma unroll
            for (int mt = 0; mt < 4; mt++)
                #pragma unroll
                for (int nt = 0; nt < 4; nt++)
                    mma_tf32(acc[mt][nt], af[mt], bf[nt]);
        }
        __syncthreads();
    }

    // ---- epilogue ----
    #pragma unroll
    for (int mt = 0; mt < 4; mt++) {
        #pragma unroll
        for (int nt = 0; nt < 4; nt++) {
            const int row = m0 + wm + mt * 16 + grp;
            const int col = n0 + wn + nt * 8 + tid4 * 2;
            float2 lo, hi;
            lo.x = acc[mt][nt][0] * alpha; lo.y = acc[mt][nt][1] * alpha;
            hi.x = acc[mt][nt][2] * alpha; hi.y = acc[mt][nt][3] * alpha;
            *(float2*)(C + (long long)row * ldc + col)       = lo;
            *(float2*)(C + (long long)(row + 8) * ldc + col) = hi;
        }
    }
}

// ---------------- fused RMSNorm + RoPE, in-place on g_qkv ----------------
__global__ void __launch_bounds__(128) norm_rope_kernel(
    const float* __restrict__ qw, const float* __restrict__ kw,
    const float* __restrict__ cosT, const float* __restrict__ sinT,
    const int* __restrict__ positions)
{
    const int tok = blockIdx.x;
    const int hh  = blockIdx.y;
    const int d   = threadIdx.x;

    float* ptr;
    const float* w;
    if (hh < NH) { ptr = g_qkv + (long long)tok * QKV_DIM + hh * HD;            w = qw; }
    else         { ptr = g_qkv + (long long)tok * QKV_DIM + NH*HD + (hh-NH)*HD; w = kw; }

    __shared__ float x[HD];
    __shared__ float red[4];

    float v = ptr[d];
    float ss = v * v;
    #pragma unroll
    for (int o = 16; o > 0; o >>= 1) ss += __shfl_xor_sync(0xffffffffu, ss, o);
    if ((d & 31) == 0) red[d >> 5] = ss;
    __syncthreads();
    float tot = red[0] + red[1] + red[2] + red[3];
    float r = rsqrtf(tot * (1.0f / HD) + EPS);
    x[d] = v * r * w[d];
    __syncthreads();

    const int pos = positions[tok];
    const int p = d >> 1;
    const float c = cosT[pos * (HD/2) + p];
    const float s = sinT[pos * (HD/2) + p];
    float out;
    if ((d & 1) == 0) out = x[d] * c - x[d + 1] * s;
    else              out = x[d - 1] * s + x[d] * c;
    ptr[d] = out;
}

// ---------------- causal softmax ----------------
// Zeroes only up to the 128-aligned tile boundary (PV never reads past it).
__global__ void __launch_bounds__(256) softmax_kernel()
{
    const int q = blockIdx.x, h = blockIdx.y;
    float* row = g_scores + ((long long)h * SQ + q) * SQ;
    const int n = q + 1;
    const int lim = ((q >> 7) + 1) << 7;   // tile-aligned upper bound
    const int t = threadIdx.x;

    __shared__ float red[8];

    float mx = -1e30f;
    for (int k = t; k < n; k += 256) mx = fmaxf(mx, row[k]);
    #pragma unroll
    for (int o = 16; o > 0; o >>= 1) mx = fmaxf(mx, __shfl_xor_sync(0xffffffffu, mx, o));
    if ((t & 31) == 0) red[t >> 5] = mx;
    __syncthreads();
    mx = red[0];
    #pragma unroll
    for (int i = 1; i < 8; i++) mx = fmaxf(mx, red[i]);
    __syncthreads();

    float sum = 0.f;
    for (int k = t; k < n; k += 256) {
        float e = expf(row[k] - mx);
        row[k] = e;
        sum += e;
    }
    #pragma unroll
    for (int o = 16; o > 0; o >>= 1) sum += __shfl_xor_sync(0xffffffffu, sum, o);
    if ((t & 31) == 0) red[t >> 5] = sum;
    __syncthreads();
    sum = red[0] + red[1] + red[2] + red[3] + red[4] + red[5] + red[6] + red[7];
    const float inv = 1.0f / sum;

    for (int k = t; k < lim; k += 256) {
        if (k < n) row[k] *= inv;
        else       row[k]  = 0.f;
    }
}

// ---------------- launch ----------------
extern "C" void kernel_launch(void* const* d_in, const int* in_sizes, int n_in,
                              void* d_out, int out_size)
{
    const float* hs     = (const float*)d_in[0];   // [2048, 2560]
    const float* w_qkv  = (const float*)d_in[1];   // [3072, 2560]
    const float* w_o    = (const float*)d_in[2];   // [2560, 2048]
    const float* qnw    = (const float*)d_in[3];
    const float* knw    = (const float*)d_in[4];
    const float* cosT   = (const float*)d_in[5];   // [4096, 64]
    const float* sinT   = (const float*)d_in[6];
    const int* positions = (const int*)d_in[9];
    float* out = (float*)d_out;                    // [2048, 2560]

    float *qkv, *scores, *att;
    cudaGetSymbolAddress((void**)&qkv,    g_qkv);
    cudaGetSymbolAddress((void**)&scores, g_scores);
    cudaGetSymbolAddress((void**)&att,    g_att);

    // 1) QKV projection: [2048,3072] = hs @ w_qkv^T
    mma_gemm<true, false, false><<<dim3(QKV_DIM/128, SQ/128, 1), 256>>>(
        hs, w_qkv, qkv, HID, HID, HID, QKV_DIM, 0, 0, 1, 0, 1.0f);

    // 2) RMSNorm + RoPE in-place
    norm_rope_kernel<<<dim3(SQ, NH + NKV), 128>>>(qnw, knw, cosT, sinT, positions);

    // 3) scores[h] = (Q_h @ K_{h/4}^T) * SCALE, causal tile skip
    mma_gemm<true, true, false><<<dim3(SQ/128, SQ/128, NH), 256>>>(
        qkv, qkv + NH*HD, scores, HD, QKV_DIM, QKV_DIM, SQ,
        HD, HD, NH/NKV, (long long)SQ * SQ, ATT_SCALE);

    // 4) causal softmax
    softmax_kernel<<<dim3(SQ, NH), 256>>>();

    // 5) att[h] = P_h @ V_{h/4}  (NN, causal-K bound)
    mma_gemm<false, false, true><<<dim3(HD/128, SQ/128, NH), 256>>>(
        scores, qkv + NH*HD + NKV*HD, att, SQ, SQ, QKV_DIM, NH*HD,
        (long long)SQ * SQ, HD, NH/NKV, HD, 1.0f);

    // 6) output projection: [2048,2560] = att @ w_o^T
    mma_gemm<true, false, false><<<dim3(HID/128, SQ/128, 1), 256>>>(
        att, w_o, out, NH*HD, NH*HD, NH*HD, HID, 0, 0, 1, 0, 1.0f);
}

// round 3
// speedup vs baseline: 2.9796x; 1.4774x over previous
#include <cuda_runtime.h>
#include <cstdint>

#define SQ   2048
#define HID  2560
#define NH   16
#define NKV  4
#define HD   128
#define QKV_DIM (NH*HD + 2*NKV*HD)   // 3072
#define EPS  1e-6f
#define ATT_SCALE 0.08838834764831845f  // 1/sqrt(128)
#define VOFF (NH*HD + NKV*HD)

// ---------------- scratch (device globals, no allocation) ----------------
__device__ float g_qkv[(size_t)SQ * QKV_DIM];            // 25 MB
__device__ float g_scores[(size_t)NH * SQ * SQ];         // 268 MB
__device__ float g_att[(size_t)SQ * NH * HD];            // 16 MB
__device__ float g_hs_r[(size_t)SQ * HID];               // 20 MB (tf32-rounded)
__device__ float g_wqkv_r[(size_t)QKV_DIM * HID];        // 30 MB
__device__ float g_wo_r[(size_t)HID * NH * HD];          // 20 MB
__device__ float g_vt[(size_t)NKV * HD * SQ];            // 4 MB  (V transposed)

__device__ __forceinline__ uint32_t f2tf32(float x) {
    uint32_t u;
    asm("cvt.rna.tf32.f32 %0, %1;" : "=r"(u) : "f"(x));
    return u;
}
__device__ __forceinline__ float roundtf(float x) { return __uint_as_float(f2tf32(x)); }

__device__ __forceinline__ void mma_tf32(float* d, const uint32_t* a, const uint32_t* b) {
    asm volatile(
        "mma.sync.aligned.m16n8k8.row.col.f32.tf32.tf32.f32 "
        "{%0,%1,%2,%3}, {%4,%5,%6,%7}, {%8,%9}, {%0,%1,%2,%3};\n"
        : "+f"(d[0]), "+f"(d[1]), "+f"(d[2]), "+f"(d[3])
        : "r"(a[0]), "r"(a[1]), "r"(a[2]), "r"(a[3]), "r"(b[0]), "r"(b[1]));
}

// ---------------- tf32 tensor-core GEMM, cp.async 2-stage pipeline ----------------
// C[m,n] = alpha * sum_k A[m,k] * B[n,k]   (both operands row-major, NT)
// Operands must already be tf32-rounded fp32 (HMMA reads raw bits).
// CAUSAL : skip N-tiles with bx > by.  CAUSALK: bound K at (by+1)*128.
// ROUND  : round C output to tf32 (for downstream GEMM consumption).
// 128x128x32 tile, 256 threads, warp = 64x32 via 4x4 m16n8k8.
// SMEM: [stage][operand][row 128][chunk 8 float4], chunk swizzle c^(row&7).
template<bool CAUSAL, bool CAUSALK, bool ROUND>
__global__ void __launch_bounds__(256, 2) mma_gemm(
    const float* __restrict__ A, const float* __restrict__ B, float* __restrict__ C,
    int K, int lda, int ldb, int ldc,
    long long aBatch, long long bBatch, int bDiv, long long cBatch, float alpha)
{
    const int bx = blockIdx.x, by = blockIdx.y, bz = blockIdx.z;
    if (CAUSAL && bx > by) return;

    A += (long long)bz * aBatch;
    B += (long long)(bz / bDiv) * bBatch;
    C += (long long)bz * cBatch;

    extern __shared__ float4 dynsmem[];
    float4 (*As)[128][8] = (float4 (*)[128][8])(dynsmem);            // [2][128][8]
    float4 (*Bs)[128][8] = (float4 (*)[128][8])(dynsmem + 2*128*8);  // [2][128][8]

    const int t    = threadIdx.x;
    const int lane = t & 31, wid = t >> 5;
    const int wm   = (wid & 1) * 64;
    const int wn   = (wid >> 1) * 32;
    const int m0   = by * 128, n0 = bx * 128;
    const int grp  = lane >> 2, tid4 = lane & 3;

    // loader mapping: thread -> (row, 4 chunks)
    const int row = t >> 1;
    const int cb  = (t & 1) * 4;
    const int x7  = row & 7;
    const float* Aptr = A + (long long)(m0 + row) * lda;
    const float* Bptr = B + (long long)(n0 + row) * ldb;

    float acc[4][4][4];
    #pragma unroll
    for (int i = 0; i < 4; i++)
        #pragma unroll
        for (int j = 0; j < 4; j++)
            #pragma unroll
            for (int r = 0; r < 4; r++) acc[i][j][r] = 0.f;

    const int Kfull = CAUSALK ? (((by + 1) * 128 < K) ? (by + 1) * 128 : K) : K;
    const int nK = Kfull >> 5;

    auto issue = [&](int st, int k0) {
        #pragma unroll
        for (int i = 0; i < 4; i++) {
            uint32_t da = (uint32_t)__cvta_generic_to_shared(&As[st][row][(cb + i) ^ x7]);
            asm volatile("cp.async.cg.shared.global [%0], [%1], 16;\n"
                         :: "r"(da), "l"(Aptr + k0 + (cb + i) * 4));
        }
        #pragma unroll
        for (int i = 0; i < 4; i++) {
            uint32_t db = (uint32_t)__cvta_generic_to_shared(&Bs[st][row][(cb + i) ^ x7]);
            asm volatile("cp.async.cg.shared.global [%0], [%1], 16;\n"
                         :: "r"(db), "l"(Bptr + k0 + (cb + i) * 4));
        }
    };

    issue(0, 0);
    asm volatile("cp.async.commit_group;\n");

    for (int kt = 0; kt < nK; kt++) {
        if (kt + 1 < nK) {
            issue((kt + 1) & 1, (kt + 1) << 5);
            asm volatile("cp.async.commit_group;\n");
            asm volatile("cp.async.wait_group 1;\n");
        } else {
            asm volatile("cp.async.wait_group 0;\n");
        }
        __syncthreads();

        const int st = kt & 1;
        const uint32_t* Aw = (const uint32_t*)(As + st);
        const uint32_t* Bw = (const uint32_t*)(Bs + st);

        #pragma unroll
        for (int j = 0; j < 4; j++) {
            const int c0 = ((2 * j)     ^ grp) * 4 + tid4;
            const int c1 = ((2 * j + 1) ^ grp) * 4 + tid4;
            uint32_t af[4][4], bf[4][2];
            #pragma unroll
            for (int mt = 0; mt < 4; mt++) {
                const int m = wm + mt * 16 + grp;
                af[mt][0] = Aw[m * 32 + c0];
                af[mt][1] = Aw[(m + 8) * 32 + c0];
                af[mt][2] = Aw[m * 32 + c1];
                af[mt][3] = Aw[(m + 8) * 32 + c1];
            }
            #pragma unroll
            for (int nt = 0; nt < 4; nt++) {
                const int nn = wn + nt * 8 + grp;
                bf[nt][0] = Bw[nn * 32 + c0];
                bf[nt][1] = Bw[nn * 32 + c1];
            }
            #pragma unroll
            for (int mt = 0; mt < 4; mt++)
                #pragma unroll
                for (int nt = 0; nt < 4; nt++)
                    mma_tf32(acc[mt][nt], af[mt], bf[nt]);
        }
        __syncthreads();
    }

    #pragma unroll
    for (int mt = 0; mt < 4; mt++) {
        #pragma unroll
        for (int nt = 0; nt < 4; nt++) {
            const int r0 = m0 + wm + mt * 16 + grp;
            const int col = n0 + wn + nt * 8 + tid4 * 2;
            float2 lo, hi;
            lo.x = acc[mt][nt][0] * alpha; lo.y = acc[mt][nt][1] * alpha;
            hi.x = acc[mt][nt][2] * alpha; hi.y = acc[mt][nt][3] * alpha;
            if (ROUND) {
                lo.x = roundtf(lo.x); lo.y = roundtf(lo.y);
                hi.x = roundtf(hi.x); hi.y = roundtf(hi.y);
            }
            *(float2*)(C + (long long)r0 * ldc + col)       = lo;
            *(float2*)(C + (long long)(r0 + 8) * ldc + col) = hi;
        }
    }
}

// ---------------- tf32 round-copy ----------------
__global__ void __launch_bounds__(256) round_copy(const float* __restrict__ src,
                                                 float* __restrict__ dst, int n4)
{
    int i = blockIdx.x * 256 + threadIdx.x;
    if (i < n4) {
        float4 v = ((const float4*)src)[i];
        v.x = roundtf(v.x); v.y = roundtf(v.y);
        v.z = roundtf(v.z); v.w = roundtf(v.w);
        ((float4*)dst)[i] = v;
    }
}

// ---------------- V transpose: g_qkv v-section -> g_vt [NKV*HD][SQ] ----------------
__global__ void __launch_bounds__(256) vt_kernel()
{
    __shared__ float tile[32][33];
    const int s0 = blockIdx.x * 32, d0 = blockIdx.y * 32;
    const int tx = threadIdx.x & 31, ty = threadIdx.x >> 5;  // 32 x 8
    #pragma unroll
    for (int r = ty; r < 32; r += 8)
        tile[r][tx] = g_qkv[(long long)(s0 + r) * QKV_DIM + VOFF + d0 + tx];
    __syncthreads();
    #pragma unroll
    for (int r = ty; r < 32; r += 8)
        g_vt[(long long)(d0 + r) * SQ + s0 + tx] = tile[tx][r];
}

// ---------------- fused RMSNorm + RoPE, in-place on g_qkv (tf32-rounded out) ----------------
__global__ void __launch_bounds__(128) norm_rope_kernel(
    const float* __restrict__ qw, const float* __restrict__ kw,
    const float* __restrict__ cosT, const float* __restrict__ sinT,
    const int* __restrict__ positions)
{
    const int tok = blockIdx.x;
    const int hh  = blockIdx.y;
    const int d   = threadIdx.x;

    float* ptr;
    const float* w;
    if (hh < NH) { ptr = g_qkv + (long long)tok * QKV_DIM + hh * HD;            w = qw; }
    else         { ptr = g_qkv + (long long)tok * QKV_DIM + NH*HD + (hh-NH)*HD; w = kw; }

    __shared__ float x[HD];
    __shared__ float red[4];

    float v = ptr[d];
    float ss = v * v;
    #pragma unroll
    for (int o = 16; o > 0; o >>= 1) ss += __shfl_xor_sync(0xffffffffu, ss, o);
    if ((d & 31) == 0) red[d >> 5] = ss;
    __syncthreads();
    float tot = red[0] + red[1] + red[2] + red[3];
    float r = rsqrtf(tot * (1.0f / HD) + EPS);
    x[d] = v * r * w[d];
    __syncthreads();

    const int pos = positions[tok];
    const int p = d >> 1;
    const float c = cosT[pos * (HD/2) + p];
    const float s = sinT[pos * (HD/2) + p];
    float out;
    if ((d & 1) == 0) out = x[d] * c - x[d + 1] * s;
    else              out = x[d - 1] * s + x[d] * c;
    ptr[d] = roundtf(out);
}

// ---------------- single-pass causal softmax (register row cache) ----------------
// grid (SQ, NH), 256 threads. Row cached in <=2 float4/thread.
// Writes P (tf32-rounded) for k<n, 0 for n<=k<lim; PV reads exactly [0,lim).
__global__ void __launch_bounds__(256) softmax_kernel()
{
    const int q = blockIdx.x, h = blockIdx.y;
    float* row = g_scores + ((long long)h * SQ + q) * SQ;
    const int n = q + 1;
    const int lim = ((q >> 7) + 1) << 7;
    const int nv = lim >> 2;
    const int t = threadIdx.x;

    __shared__ float red[8];

    float4 v[2];
    float mx = -1e30f;
    #pragma unroll
    for (int i = 0; i < 2; i++) {
        const int idx = t + i * 256;
        if (idx < nv) {
            float4 u = ((const float4*)row)[idx];
            const int k = idx * 4;
            u.x = (k + 0 < n) ? u.x : -1e30f;
            u.y = (k + 1 < n) ? u.y : -1e30f;
            u.z = (k + 2 < n) ? u.z : -1e30f;
            u.w = (k + 3 < n) ? u.w : -1e30f;
            mx = fmaxf(mx, fmaxf(fmaxf(u.x, u.y), fmaxf(u.z, u.w)));
            v[i] = u;
        }
    }
    #pragma unroll
    for (int o = 16; o > 0; o >>= 1) mx = fmaxf(mx, __shfl_xor_sync(0xffffffffu, mx, o));
    if ((t & 31) == 0) red[t >> 5] = mx;
    __syncthreads();
    mx = red[0];
    #pragma unroll
    for (int i = 1; i < 8; i++) mx = fmaxf(mx, red[i]);

    float sum = 0.f;
    #pragma unroll
    for (int i = 0; i < 2; i++) {
        const int idx = t + i * 256;
        if (idx < nv) {
            float4 u = v[i];
            u.x = __expf(u.x - mx); u.y = __expf(u.y - mx);
            u.z = __expf(u.z - mx); u.w = __expf(u.w - mx);
            sum += (u.x + u.y) + (u.z + u.w);
            v[i] = u;
        }
    }
    __syncthreads();
    #pragma unroll
    for (int o = 16; o > 0; o >>= 1) sum += __shfl_xor_sync(0xffffffffu, sum, o);
    if ((t & 31) == 0) red[t >> 5] = sum;
    __syncthreads();
    sum = red[0] + red[1] + red[2] + red[3] + red[4] + red[5] + red[6] + red[7];
    const float inv = 1.0f / sum;

    #pragma unroll
    for (int i = 0; i < 2; i++) {
        const int idx = t + i * 256;
        if (idx < nv) {
            float4 u = v[i];
            u.x = roundtf(u.x * inv); u.y = roundtf(u.y * inv);
            u.z = roundtf(u.z * inv); u.w = roundtf(u.w * inv);
            ((float4*)row)[idx] = u;
        }
    }
}

// ---------------- launch ----------------
extern "C" void kernel_launch(void* const* d_in, const int* in_sizes, int n_in,
                              void* d_out, int out_size)
{
    const float* hs     = (const float*)d_in[0];   // [2048, 2560]
    const float* w_qkv  = (const float*)d_in[1];   // [3072, 2560]
    const float* w_o    = (const float*)d_in[2];   // [2560, 2048]
    const float* qnw    = (const float*)d_in[3];
    const float* knw    = (const float*)d_in[4];
    const float* cosT   = (const float*)d_in[5];   // [4096, 64]
    const float* sinT   = (const float*)d_in[6];
    const int* positions = (const int*)d_in[9];
    float* out = (float*)d_out;                    // [2048, 2560]

    float *qkv, *scores, *att, *hs_r, *wqkv_r, *wo_r, *vt;
    cudaGetSymbolAddress((void**)&qkv,    g_qkv);
    cudaGetSymbolAddress((void**)&scores, g_scores);
    cudaGetSymbolAddress((void**)&att,    g_att);
    cudaGetSymbolAddress((void**)&hs_r,   g_hs_r);
    cudaGetSymbolAddress((void**)&wqkv_r, g_wqkv_r);
    cudaGetSymbolAddress((void**)&wo_r,   g_wo_r);
    cudaGetSymbolAddress((void**)&vt,     g_vt);

    const int SMEM = 2 * 2 * 128 * 8 * 16;  // 64 KB
    cudaFuncSetAttribute(mma_gemm<false, false, true >, cudaFuncAttributeMaxDynamicSharedMemorySize, SMEM);
    cudaFuncSetAttribute(mma_gemm<true,  false, false>, cudaFuncAttributeMaxDynamicSharedMemorySize, SMEM);
    cudaFuncSetAttribute(mma_gemm<false, true,  true >, cudaFuncAttributeMaxDynamicSharedMemorySize, SMEM);
    cudaFuncSetAttribute(mma_gemm<false, false, false>, cudaFuncAttributeMaxDynamicSharedMemorySize, SMEM);

    // 0) tf32-round the raw fp32 operands
    round_copy<<<(SQ*HID/4 + 255)/256, 256>>>(hs, hs_r, SQ*HID/4);
    round_copy<<<(QKV_DIM*HID/4 + 255)/256, 256>>>(w_qkv, wqkv_r, QKV_DIM*HID/4);
    round_copy<<<(HID*NH*HD/4 + 255)/256, 256>>>(w_o, wo_r, HID*NH*HD/4);

    // 1) QKV projection: [2048,3072] = hs @ w_qkv^T   (epilogue rounds -> q,k,v tf32)
    mma_gemm<false, false, true><<<dim3(QKV_DIM/128, SQ/128, 1), 256, SMEM>>>(
        hs_r, wqkv_r, qkv, HID, HID, HID, QKV_DIM, 0, 0, 1, 0, 1.0f);

    // 2) RMSNorm + RoPE in-place (rounds q,k)
    norm_rope_kernel<<<dim3(SQ, NH + NKV), 128>>>(qnw, knw, cosT, sinT, positions);

    // 3) V transpose -> g_vt [NKV*HD][SQ]
    vt_kernel<<<dim3(SQ/32, NKV*HD/32), 256>>>();

    // 4) scores[h] = (Q_h @ K_{h/4}^T) * SCALE, causal tile skip
    mma_gemm<true, false, false><<<dim3(SQ/128, SQ/128, NH), 256, SMEM>>>(
        qkv, qkv + NH*HD, scores, HD, QKV_DIM, QKV_DIM, SQ,
        HD, HD, NH/NKV, (long long)SQ * SQ, ATT_SCALE);

    // 5) causal softmax (rounds P)
    softmax_kernel<<<dim3(SQ, NH), 256>>>();

    // 6) att[h] = P_h @ V_{h/4}  (B = Vt, causal-K bound; epilogue rounds)
    mma_gemm<false, true, true><<<dim3(HD/128, SQ/128, NH), 256, SMEM>>>(
        scores, vt, att, SQ, SQ, SQ, NH*HD,
        (long long)SQ * SQ, (long long)HD * SQ, NH/NKV, HD, 1.0f);

    // 7) output projection: [2048,2560] = att @ w_o^T
    mma_gemm<false, false, false><<<dim3(HID/128, SQ/128, 1), 256, SMEM>>>(
        att, wo_r, out, NH*HD, NH*HD, NH*HD, HID, 0, 0, 1, 0, 1.0f);
}